// round 16
// baseline (speedup 1.0000x reference)
#include <cuda_runtime.h>
#include <cstdint>

#define BATCH 32
#define NBOX 25200
#define MAXB 100
#define PUSH_T 66.0f   // exp ~383 candidates/batch, sigma~19; CAP margin 6.6 sigma
#define CAP 512        // per-batch candidate capacity (sort width)
#define KTOP 256       // conflict matrix over top-KTOP sorted candidates
#define J1 160         // lazy matrix cutoff (greedy is prefix-stable)
#define TPB 512
#define SBLKS 50       // scoring blocks per batch: 50*512 >= 25200

typedef unsigned long long u64;

// scratch (allocation-free rule -> __device__ globals; zero-init at load,
// counters reset by tail blocks every run so graph replays stay valid)
__device__ u64 g_cand[BATCH * CAP];
__device__ int g_cnt[BATCH];
__device__ int g_arrive[BATCH];

// ---------------------------------------------------------------------------
// Heterogeneous single launch: bids 0..31 = per-batch tail blocks (spin-wait
// on their batch's 50 producers, then sort/matrix/sweep/output); bids 32+ =
// scoring blocks (proven thread-per-row scorer). Tails overlap scoring of
// later batches; no deadlock (32 spinning blocks << 148 SMs).
// ---------------------------------------------------------------------------
__global__ void __launch_bounds__(TPB, 2)
nms_all(const float* __restrict__ p, const float* __restrict__ c,
        const float* __restrict__ boxes, float* __restrict__ out,
        int out_size) {
    __shared__ u64 s_buf[2][CAP];       // 8KB sort double-buffer
    __shared__ u64 s_mask[KTOP * 4];    // 8KB conflict bits (lower triangle)
    __shared__ float4 s_box[KTOP];      // 4KB
    __shared__ float  s_cs[KTOP];       // 1KB
    __shared__ float  s_area[KTOP];     // 1KB
    __shared__ unsigned s_sel32[8], s_new32[8];
    __shared__ int s_stop, s_tot;

    const int tid = threadIdx.x;

    // ======================= SCORING PATH (bids >= 32) =====================
    if (blockIdx.x >= BATCH) {
        const int sid = blockIdx.x - BATCH;
        const int b = sid / SBLKS;
        const int blk = sid % SBLKS;
        const int r = blk * TPB + tid;
        if (r < NBOX) {
            const float pv = p[(size_t)b * NBOX + r];
            // exact prefilter: score = p*argmax_idx <= p*79 (monotone fp)
            if (pv * 79.0f > PUSH_T) {
                const float4* rb =
                    reinterpret_cast<const float4*>(c) + ((size_t)b * NBOX + r) * 20;
                float mx = -3.402823466e38f;
                int bi = 0;
                #pragma unroll
                for (int h = 0; h < 2; h++) {
                    float4 v[10];
                    #pragma unroll
                    for (int i = 0; i < 10; i++) v[i] = rb[h * 10 + i];
                    float hm = v[0].x;
                    #pragma unroll
                    for (int i = 0; i < 10; i++) {
                        float m4 = fmaxf(fmaxf(v[i].x, v[i].y), fmaxf(v[i].z, v[i].w));
                        hm = fmaxf(hm, m4);
                    }
                    int hb = 0;
                    #pragma unroll
                    for (int i = 9; i >= 0; i--) {   // descending: lowest idx wins
                        int base = (h * 10 + i) * 4;
                        if (v[i].w == hm) hb = base + 3;
                        if (v[i].z == hm) hb = base + 2;
                        if (v[i].y == hm) hb = base + 1;
                        if (v[i].x == hm) hb = base + 0;
                    }
                    if (hm > mx) { mx = hm; bi = hb; }  // strict >: half0 on ties
                }
                const float score = pv * (float)bi;
                if (score > PUSH_T) {
                    const int pos = atomicAdd(&g_cnt[b], 1);
                    if (pos < CAP) {
                        unsigned sb = __float_as_uint(score);  // >0 => monotone
                        g_cand[b * CAP + pos] = ((u64)(~sb) << 32) | (unsigned)r;
                    }
                }
            }
        }
        __syncthreads();
        if (tid == 0) {
            __threadfence();                        // release candidate writes
            atomicAdd(&g_arrive[b], 1);
        }
        return;
    }

    // ========================= TAIL PATH (bids 0..31) ======================
    const int b = blockIdx.x;
    const float4* bx = reinterpret_cast<const float4*>(boxes) + (size_t)b * NBOX;
    float* pred = out + (size_t)b * MAXB * 6;

    if (tid == 0) {                                 // spin until producers done
        while (true) {
            int v;
            asm volatile("ld.global.acquire.gpu.b32 %0, [%1];"
                         : "=r"(v) : "l"(&g_arrive[b]) : "memory");
            if (v == SBLKS) break;
            __nanosleep(128);
        }
    }
    __syncthreads();
    __threadfence();                                // acquire candidate writes

    const int cnt = min(g_cnt[b], CAP);
    const int limit = min(cnt, KTOP);

    // ---------------- sort 512 keys (512 threads own them) ----------------
    u64 key = (tid < cnt) ? g_cand[(size_t)b * CAP + tid] : 0xFFFFFFFFFFFFFFFFULL;
    int ph = 0;
    #pragma unroll 1
    for (int k = 2; k <= CAP; k <<= 1) {
        const bool up = ((tid & k) == 0);
        int j = k >> 1;
        #pragma unroll 1
        for (; j >= 32; j >>= 1) {                  // cross-warp: SMEM
            s_buf[ph][tid] = key;
            __syncthreads();
            u64 partner = s_buf[ph][tid ^ j];
            bool keep_min = (up == ((tid & j) == 0));
            key = keep_min ? (key < partner ? key : partner)
                           : (key > partner ? key : partner);
            ph ^= 1;
        }
        #pragma unroll 1
        for (; j >= 1; j >>= 1) {                   // intra-warp: shfl
            u64 partner = __shfl_xor_sync(0xffffffffu, key, j);
            bool keep_min = (up == ((tid & j) == 0));
            key = keep_min ? (key < partner ? key : partner)
                           : (key > partner ? key : partner);
        }
    }

    // ---------------- gather top-256 + areas + zero output ----------------
    if (tid < KTOP) {
        unsigned idx = (unsigned)(key & 0xFFFFFFFFu);
        s_cs[tid] = __uint_as_float(~(unsigned)(key >> 32));
        float4 z = make_float4(0.f, 0.f, 0.f, 0.f);
        float4 cb = (tid < limit && idx < NBOX) ? bx[idx] : z;
        s_box[tid] = cb;
        s_area[tid] = (cb.z - cb.x) * (cb.w - cb.y);
    }
    for (int i = tid; i < MAXB * 6; i += TPB) pred[i] = 0.0f;  // d_out poisoned
    __syncthreads();

    // ---- matrix rows [rlo,rhi): broadcast mapping, lower triangle,
    //      512 threads -> each covers 2 words (h loop) ----
    #define MATRIX_ROWS(rlo, rhi)                                             \
    {                                                                         \
        const int j = tid & 255;                                              \
        const int w0 = tid >> 8;               /* 0..1, const within warp */  \
        if (j >= (rlo) && j < (rhi)) {                                        \
            float4 cb = s_box[j];                                             \
            float area_c = s_area[j];                                         \
            _Pragma("unroll")                                                 \
            for (int h = 0; h < 2; h++) {                                     \
                const int w = w0 * 2 + h;                                     \
                u64 m = 0ull;                                                 \
                const int qmax = min(64, j - w * 64);   /* only i < j */      \
                for (int q = 0; q < qmax; q++) {                              \
                    float4 ob = s_box[w * 64 + q];      /* warp-broadcast */  \
                    float iy = fmaxf(0.0f, fminf(ob.z, cb.z) - fmaxf(ob.x, cb.x));\
                    float ix = fmaxf(0.0f, fminf(ob.w, cb.w) - fmaxf(ob.y, cb.y));\
                    float inter = iy * ix;                                    \
                    float uni = area_c + s_area[w * 64 + q] - inter;          \
                    if (uni > 0.0f && inter + inter > uni) m |= (1ull << q);  \
                }                                                             \
                s_mask[j * 4 + w] = m;                                        \
            }                                                                 \
        }                                                                     \
    }

    #define PREF_BUILD(rmax)                                                  \
    if (tid < (rmax)) {                                                       \
        _Pragma("unroll")                                                     \
        for (int w8 = 0; w8 < 8; w8++) {                                      \
            u64 word = s_mask[tid * 4 + (w8 >> 1)];                           \
            unsigned half = (w8 & 1) ? (unsigned)(word >> 32) : (unsigned)word;\
            int base = w8 * 32;                                               \
            if (base + 32 <= tid)      pref[w8] = half;                       \
            else if (base >= tid)      pref[w8] = 0u;                         \
            else                       pref[w8] = half & ((1u << (tid - base)) - 1);\
        }                                                                     \
    }

    #define JACOBI(NW, le)                                                    \
    {                                                                         \
        if (tid < 8) s_sel32[tid] = ((le) >= (int)(tid + 1) * 32) ? 0xFFFFFFFFu\
                                  : ((le) > (int)tid * 32)                    \
                                    ? ((1u << ((le) - tid * 32)) - 1) : 0u;   \
        if (tid == 0) s_stop = 0;                                             \
        __syncthreads();                                                      \
        _Pragma("unroll 1")                                                   \
        for (int round = 0; round < 260; round++) {                           \
            if (tid < KTOP) {                                                 \
                unsigned acc = 0;                                             \
                _Pragma("unroll")                                             \
                for (int w8 = 0; w8 < (NW); w8++) acc |= pref[w8] & s_sel32[w8];\
                bool nb = (tid < (le)) && (acc == 0u);                        \
                unsigned bal = __ballot_sync(0xffffffffu, nb);                \
                if ((tid & 31) == 0) s_new32[tid >> 5] = bal;                 \
            }                                                                 \
            __syncthreads();                                                  \
            if (tid < 32) {                                                   \
                bool eq = true;                                               \
                if (tid < 8) {                                                \
                    eq = (s_new32[tid] == s_sel32[tid]);                      \
                    s_sel32[tid] = s_new32[tid];                              \
                }                                                             \
                unsigned bal = __ballot_sync(0xffffffffu, eq);                \
                if (tid == 0) s_stop = ((bal & 0xFFu) == 0xFFu) ? 1 : 0;      \
            }                                                                 \
            __syncthreads();                                                  \
            if (s_stop) break;                                                \
        }                                                                     \
    }

    unsigned pref[8];
    #pragma unroll
    for (int w8 = 0; w8 < 8; w8++) pref[w8] = 0u;

    // fast path: rows < J1 (greedy is prefix-stable)
    MATRIX_ROWS(0, J1);
    __syncthreads();
    PREF_BUILD(J1);
    const int lim1 = min(limit, J1);
    JACOBI(5, lim1);

    if (tid == 0) {
        int tot = 0;
        #pragma unroll
        for (int w8 = 0; w8 < 8; w8++) tot += __popc(s_sel32[w8]);
        s_tot = tot;
    }
    __syncthreads();

    if (s_tot < MAXB && limit > J1) {   // rare exact fallback
        MATRIX_ROWS(J1, KTOP);
        __syncthreads();
        PREF_BUILD(KTOP);
        JACOBI(8, limit);
        if (tid == 0) {
            int tot = 0;
            #pragma unroll
            for (int w8 = 0; w8 < 8; w8++) tot += __popc(s_sel32[w8]);
            s_tot = tot;
        }
        __syncthreads();
    }

    // ---------------- popcount-ranked parallel output ----------------
    if (tid < KTOP) {
        int w8 = tid >> 5, bit = tid & 31;
        bool selb = (s_sel32[w8] >> bit) & 1u;
        if (selb) {
            int rank = 0;
            #pragma unroll
            for (int w = 0; w < 8; w++)
                if (w < w8) rank += __popc(s_sel32[w]);
            rank += __popc(s_sel32[w8] & ((bit == 0) ? 0u : ((1u << bit) - 1)));
            if (rank < MAXB) {
                float4 cb = s_box[tid];
                float* o = pred + rank * 6;
                o[0] = fminf(fmaxf(cb.x, 0.0f), 1.0f);
                o[1] = fminf(fmaxf(cb.y, 0.0f), 1.0f);
                o[2] = fminf(fmaxf(cb.z, 0.0f), 1.0f);
                o[3] = fminf(fmaxf(cb.w, 0.0f), 1.0f);
                o[4] = s_cs[tid];
                o[5] = 0.0f;
            }
        }
    }
    if (tid == 0) {
        if (out_size >= BATCH * MAXB * 6 + BATCH)
            out[BATCH * MAXB * 6 + b] = (float)min(s_tot, MAXB);
        g_cnt[b] = 0;                      // reset for next graph replay
        g_arrive[b] = 0;
    }
}

// ---------------------------------------------------------------------------
extern "C" void kernel_launch(void* const* d_in, const int* in_sizes, int n_in,
                              void* d_out, int out_size) {
    const float* bbox = (const float*)d_in[0];   // [32,25200,4]
    const float* p    = (const float*)d_in[1];   // [32,25200,1]
    const float* c    = (const float*)d_in[2];   // [32,25200,80]
    float* out = (float*)d_out;

    nms_all<<<BATCH + BATCH * SBLKS, TPB>>>(p, c, bbox, out, out_size);
}